// round 1
// baseline (speedup 1.0000x reference)
#include <cuda_runtime.h>
#include <cstddef>

#define NN 100000
#define NE 1000000
#define DD 300
#define DV (DD/4)   // 75 float4 per row

// ---------------- scratch (device globals; no allocation allowed) ----------
__device__ __align__(16) float g_deg[4 * NN];                 // [out_r | in_r | out_c | in_c]
__device__ __align__(16) float g_agg_r[(size_t)NN * DD];
__device__ __align__(16) float g_agg_c[(size_t)NN * DD];
__device__ __align__(16) float g_rowg[(size_t)NN * DD];
__device__ __align__(16) float g_colg[(size_t)NN * DD];
__device__ __align__(16) float g_merged[(size_t)NN * 2 * DD];

// ---------------- zero ------------------------------------------------------
__global__ void zero_kernel(float4* __restrict__ p, long n4) {
    long i = (long)blockIdx.x * blockDim.x + threadIdx.x;
    long stride = (long)gridDim.x * blockDim.x;
    float4 z = make_float4(0.f, 0.f, 0.f, 0.f);
    for (; i < n4; i += stride) p[i] = z;
}

// ---------------- degrees ---------------------------------------------------
__global__ void degree_kernel(const int* __restrict__ er, const int* __restrict__ ec) {
    int i = blockIdx.x * blockDim.x + threadIdx.x;
    if (i < NE) {
        atomicAdd(&g_deg[0 * NN + er[i]],      1.f);  // out-deg row graph (src)
        atomicAdd(&g_deg[1 * NN + er[NE + i]], 1.f);  // in-deg  row graph (dst)
        atomicAdd(&g_deg[2 * NN + ec[i]],      1.f);  // out-deg col graph
        atomicAdd(&g_deg[3 * NN + ec[NE + i]], 1.f);  // in-deg  col graph
    }
}

__global__ void norm_kernel() {
    int i = blockIdx.x * blockDim.x + threadIdx.x;
    if (i < 4 * NN) {
        float d = g_deg[i];
        g_deg[i] = (d > 0.f) ? rsqrtf(d) : 0.f;
    }
}

// ---------------- edge scatter:  agg[dst] += x[src] * norm_src[src] ---------
__global__ void scatter_kernel(const int* __restrict__ src, const int* __restrict__ dst,
                               const float* __restrict__ nsrc,
                               const float4* __restrict__ x, float4* __restrict__ agg) {
    long i = (long)blockIdx.x * blockDim.x + threadIdx.x;
    if (i >= (long)NE * DV) return;
    int e = (int)(i / DV);
    int c = (int)(i - (long)e * DV);
    int s = src[e];
    int d = dst[e];
    float ns = nsrc[s];
    float4 v = x[(size_t)s * DV + c];
    float4* p = &agg[(size_t)d * DV + c];
    asm volatile("red.global.add.v4.f32 [%0], {%1, %2, %3, %4};"
                 :: "l"(p), "f"(v.x * ns), "f"(v.y * ns), "f"(v.z * ns), "f"(v.w * ns)
                 : "memory");
}

// ---------------- GEMM: C = act( (A * rowScale) @ B + bias ) ----------------
// A: M x K (row-major, lda), B: K x Ncols (row-major, ldb), C: M x Ncols (ldc)
#define BM 64
#define BN 64
#define BK 16

__global__ __launch_bounds__(256) void gemm_kernel(
    const float* __restrict__ A, int lda,
    const float* __restrict__ rowScale,
    const float* __restrict__ B, int ldb,
    const float* __restrict__ bias,
    float* __restrict__ C, int ldc,
    int M, int Ncols, int K, int relu)
{
    __shared__ float As[BK][BM];
    __shared__ float Bs[BK][BN];

    int t  = threadIdx.x;
    int m0 = blockIdx.y * BM;
    int n0 = blockIdx.x * BN;
    int tx = t & 15;        // 16 col-threads
    int ty = t >> 4;        // 16 row-threads

    // A loader: thread loads one float4 along K.  am in [0,64), akv in [0,4)
    int am  = t >> 2;
    int akv = t & 3;
    int arow = m0 + am;
    float ascale = 1.f;
    if (rowScale != nullptr && arow < M) ascale = rowScale[arow];

    // B loader: bk in [0,16), bnv in [0,16)
    int bk  = t >> 4;
    int bnv = t & 15;

    float acc[4][4];
    #pragma unroll
    for (int i = 0; i < 4; i++)
        #pragma unroll
        for (int j = 0; j < 4; j++) acc[i][j] = 0.f;

    for (int k0 = 0; k0 < K; k0 += BK) {
        // load A tile (with row scale), zero-fill out of bounds
        float4 a = make_float4(0.f, 0.f, 0.f, 0.f);
        int ak = k0 + akv * 4;
        if (arow < M && ak < K)
            a = *(const float4*)(A + (size_t)arow * lda + ak);
        As[akv * 4 + 0][am] = a.x * ascale;
        As[akv * 4 + 1][am] = a.y * ascale;
        As[akv * 4 + 2][am] = a.z * ascale;
        As[akv * 4 + 3][am] = a.w * ascale;

        // load B tile
        float4 b = make_float4(0.f, 0.f, 0.f, 0.f);
        int brow = k0 + bk;
        int bcol = n0 + bnv * 4;
        if (brow < K && bcol < Ncols)
            b = *(const float4*)(B + (size_t)brow * ldb + bcol);
        *(float4*)&Bs[bk][bnv * 4] = b;

        __syncthreads();

        #pragma unroll
        for (int kk = 0; kk < BK; kk++) {
            float4 av = *(const float4*)&As[kk][ty * 4];
            float4 bv = *(const float4*)&Bs[kk][tx * 4];
            acc[0][0] += av.x * bv.x; acc[0][1] += av.x * bv.y;
            acc[0][2] += av.x * bv.z; acc[0][3] += av.x * bv.w;
            acc[1][0] += av.y * bv.x; acc[1][1] += av.y * bv.y;
            acc[1][2] += av.y * bv.z; acc[1][3] += av.y * bv.w;
            acc[2][0] += av.z * bv.x; acc[2][1] += av.z * bv.y;
            acc[2][2] += av.z * bv.z; acc[2][3] += av.z * bv.w;
            acc[3][0] += av.w * bv.x; acc[3][1] += av.w * bv.y;
            acc[3][2] += av.w * bv.z; acc[3][3] += av.w * bv.w;
        }
        __syncthreads();
    }

    #pragma unroll
    for (int i = 0; i < 4; i++) {
        int m = m0 + ty * 4 + i;
        if (m < M) {
            #pragma unroll
            for (int j = 0; j < 4; j++) {
                int n = n0 + tx * 4 + j;
                if (n < Ncols) {
                    float v = acc[i][j] + bias[n];
                    if (relu) v = fmaxf(v, 0.f);
                    C[(size_t)m * ldc + n] = v;
                }
            }
        }
    }
}

// ---------------- LayerNorm (one warp per row of DD=300 cols) ---------------
__global__ void ln_kernel(float* __restrict__ X, int ld,
                          const float* __restrict__ gamma,
                          const float* __restrict__ beta, int M) {
    int warp = (int)((blockIdx.x * (long)blockDim.x + threadIdx.x) >> 5);
    int lane = threadIdx.x & 31;
    if (warp >= M) return;
    float* p = X + (size_t)warp * ld;

    float v[10];
    float sum = 0.f;
    #pragma unroll
    for (int k = 0; k < 10; k++) {
        int c = lane + 32 * k;
        v[k] = (c < DD) ? p[c] : 0.f;
        sum += v[k];
    }
    #pragma unroll
    for (int o = 16; o > 0; o >>= 1) sum += __shfl_xor_sync(0xFFFFFFFFu, sum, o);
    float mu = sum * (1.f / DD);

    float var = 0.f;
    #pragma unroll
    for (int k = 0; k < 10; k++) {
        int c = lane + 32 * k;
        float d = (c < DD) ? (v[k] - mu) : 0.f;
        var += d * d;
    }
    #pragma unroll
    for (int o = 16; o > 0; o >>= 1) var += __shfl_xor_sync(0xFFFFFFFFu, var, o);
    float rsig = rsqrtf(var * (1.f / DD) + 1e-5f);

    #pragma unroll
    for (int k = 0; k < 10; k++) {
        int c = lane + 32 * k;
        if (c < DD) p[c] = (v[k] - mu) * rsig * gamma[c] + beta[c];
    }
}

// ---------------- launch ----------------------------------------------------
extern "C" void kernel_launch(void* const* d_in, const int* in_sizes, int n_in,
                              void* d_out, int out_size) {
    const float* x    = (const float*)d_in[0];
    const int*   er   = (const int*)d_in[1];
    const int*   ec   = (const int*)d_in[2];
    const float* Wr   = (const float*)d_in[3];
    const float* br   = (const float*)d_in[4];
    const float* Wc   = (const float*)d_in[5];
    const float* bc   = (const float*)d_in[6];
    const float* Wrs  = (const float*)d_in[7];
    const float* brs  = (const float*)d_in[8];
    const float* g_rs = (const float*)d_in[9];
    const float* b_rs = (const float*)d_in[10];
    const float* Wcs  = (const float*)d_in[11];
    const float* bcs  = (const float*)d_in[12];
    const float* g_cs = (const float*)d_in[13];
    const float* b_cs = (const float*)d_in[14];
    const float* Wm   = (const float*)d_in[15];
    const float* bm   = (const float*)d_in[16];
    const float* g_m  = (const float*)d_in[17];
    const float* b_m  = (const float*)d_in[18];
    float* out = (float*)d_out;

    float *deg, *aggr, *aggc, *rowg, *colg, *merged;
    cudaGetSymbolAddress((void**)&deg,    g_deg);
    cudaGetSymbolAddress((void**)&aggr,   g_agg_r);
    cudaGetSymbolAddress((void**)&aggc,   g_agg_c);
    cudaGetSymbolAddress((void**)&rowg,   g_rowg);
    cudaGetSymbolAddress((void**)&colg,   g_colg);
    cudaGetSymbolAddress((void**)&merged, g_merged);

    // zero degree + aggregation buffers
    zero_kernel<<<1024, 256>>>((float4*)deg, (long)(4 * NN) / 4);
    zero_kernel<<<29297, 256>>>((float4*)aggr, (long)NN * DV);
    zero_kernel<<<29297, 256>>>((float4*)aggc, (long)NN * DV);

    // degrees -> rsqrt norms
    degree_kernel<<<(NE + 255) / 256, 256>>>(er, ec);
    norm_kernel<<<(4 * NN + 255) / 256, 256>>>();

    // edge scatter (agg[dst] += x[src]*norm_src[src])
    long sw = (long)NE * DV;
    int sgrid = (int)((sw + 255) / 256);
    scatter_kernel<<<sgrid, 256>>>(er, er + NE, deg + 0 * NN, (const float4*)x, (float4*)aggr);
    scatter_kernel<<<sgrid, 256>>>(ec, ec + NE, deg + 2 * NN, (const float4*)x, (float4*)aggc);

    dim3 ggrid((DD + BN - 1) / BN, (NN + BM - 1) / BM);

    // GraphConv GEMMs: relu((agg * norm_dst) @ W + b)
    gemm_kernel<<<ggrid, 256>>>(aggr, DD, deg + 1 * NN, Wr, DD, br, rowg, DD, NN, DD, DD, 1);
    gemm_kernel<<<ggrid, 256>>>(aggc, DD, deg + 3 * NN, Wc, DD, bc, colg, DD, NN, DD, DD, 1);

    // support GEMMs into merged buffer halves, then LayerNorm in place
    gemm_kernel<<<ggrid, 256>>>(rowg, DD, nullptr, Wrs, DD, brs, merged,       2 * DD, NN, DD, DD, 0);
    gemm_kernel<<<ggrid, 256>>>(colg, DD, nullptr, Wcs, DD, bcs, merged + DD,  2 * DD, NN, DD, DD, 0);
    int lngrid = (NN + 7) / 8;  // 8 warps (rows) per 256-thread block
    ln_kernel<<<lngrid, 256>>>(merged,      2 * DD, g_rs, b_rs, NN);
    ln_kernel<<<lngrid, 256>>>(merged + DD, 2 * DD, g_cs, b_cs, NN);

    // merge GEMM (K=600) + final LayerNorm into output
    gemm_kernel<<<ggrid, 256>>>(merged, 2 * DD, nullptr, Wm, DD, bm, out, DD, NN, DD, 2 * DD, 0);
    ln_kernel<<<lngrid, 256>>>(out, DD, g_m, b_m, NN);
}

// round 2
// speedup vs baseline: 1.6558x; 1.6558x over previous
#include <cuda_runtime.h>
#include <cuda_bf16.h>
#include <cstddef>
#include <cstdint>

#define NN 100000
#define NE 1000000
#define DD 300
#define DV (DD/4)   // 75 float4 per row

// ---------------- scratch (device globals; no allocation allowed) ----------
__device__ __align__(16) float g_deg[4 * NN];                 // [out_r | in_r | out_c | in_c]
__device__ __align__(16) float g_agg_r[(size_t)NN * DD];
__device__ __align__(16) float g_agg_c[(size_t)NN * DD];
__device__ __align__(16) float g_rowg[(size_t)NN * DD];
__device__ __align__(16) float g_colg[(size_t)NN * DD];
__device__ __align__(16) float g_merged[(size_t)NN * 2 * DD];

// ---------------- zero ------------------------------------------------------
__global__ void zero_kernel(float4* __restrict__ p, long n4) {
    long i = (long)blockIdx.x * blockDim.x + threadIdx.x;
    long stride = (long)gridDim.x * blockDim.x;
    float4 z = make_float4(0.f, 0.f, 0.f, 0.f);
    for (; i < n4; i += stride) p[i] = z;
}

// ---------------- degrees ---------------------------------------------------
__global__ void degree_kernel(const int* __restrict__ er, const int* __restrict__ ec) {
    int i = blockIdx.x * blockDim.x + threadIdx.x;
    if (i < NE) {
        atomicAdd(&g_deg[0 * NN + er[i]],      1.f);
        atomicAdd(&g_deg[1 * NN + er[NE + i]], 1.f);
        atomicAdd(&g_deg[2 * NN + ec[i]],      1.f);
        atomicAdd(&g_deg[3 * NN + ec[NE + i]], 1.f);
    }
}

__global__ void norm_kernel() {
    int i = blockIdx.x * blockDim.x + threadIdx.x;
    if (i < 4 * NN) {
        float d = g_deg[i];
        g_deg[i] = (d > 0.f) ? rsqrtf(d) : 0.f;
    }
}

// ---------------- edge scatter:  agg[dst] += x[src] * norm_src[src] ---------
__global__ void scatter_kernel(const int* __restrict__ src, const int* __restrict__ dst,
                               const float* __restrict__ nsrc,
                               const float4* __restrict__ x, float4* __restrict__ agg) {
    long i = (long)blockIdx.x * blockDim.x + threadIdx.x;
    if (i >= (long)NE * DV) return;
    int e = (int)(i / DV);
    int c = (int)(i - (long)e * DV);
    int s = src[e];
    int d = dst[e];
    float ns = nsrc[s];
    float4 v = x[(size_t)s * DV + c];
    float4* p = &agg[(size_t)d * DV + c];
    asm volatile("red.global.add.v4.f32 [%0], {%1, %2, %3, %4};"
                 :: "l"(p), "f"(v.x * ns), "f"(v.y * ns), "f"(v.z * ns), "f"(v.w * ns)
                 : "memory");
}

// ================= Tensor-core GEMM ==========================================
// C = act( (A * rowScale) @ B + bias )  in fp32 via 3-pass bf16 split:
// A = Ah + Al, B = Bh + Bl;  C ~= Ah@Bh + Ah@Bl + Al@Bh   (err ~ 2^-18)
// A: M x K row-major (lda), B: K x Ncols row-major (ldb), C: M x Ncols (ldc)
#define GBM 128
#define GBN 64
#define GBK 32
#define APAD 8
#define BPAD 8
#define ASTR (GBK + APAD)   // 40 halves per A row
#define BSTR (GBN + BPAD)   // 72 halves per B row

__device__ __forceinline__ void ldsm_x4(uint32_t& r0, uint32_t& r1, uint32_t& r2, uint32_t& r3,
                                        uint32_t addr) {
    asm volatile("ldmatrix.sync.aligned.m8n8.x4.shared.b16 {%0,%1,%2,%3}, [%4];"
                 : "=r"(r0), "=r"(r1), "=r"(r2), "=r"(r3) : "r"(addr));
}
__device__ __forceinline__ void ldsm_x4_t(uint32_t& r0, uint32_t& r1, uint32_t& r2, uint32_t& r3,
                                          uint32_t addr) {
    asm volatile("ldmatrix.sync.aligned.m8n8.x4.trans.shared.b16 {%0,%1,%2,%3}, [%4];"
                 : "=r"(r0), "=r"(r1), "=r"(r2), "=r"(r3) : "r"(addr));
}
__device__ __forceinline__ void mma_bf16(float* c, const uint32_t* a, const uint32_t* b) {
    asm volatile("mma.sync.aligned.m16n8k16.row.col.f32.bf16.bf16.f32 "
                 "{%0,%1,%2,%3}, {%4,%5,%6,%7}, {%8,%9}, {%0,%1,%2,%3};"
                 : "+f"(c[0]), "+f"(c[1]), "+f"(c[2]), "+f"(c[3])
                 : "r"(a[0]), "r"(a[1]), "r"(a[2]), "r"(a[3]), "r"(b[0]), "r"(b[1]));
}

__global__ __launch_bounds__(256) void gemm_tc_kernel(
    const float* __restrict__ A, int lda,
    const float* __restrict__ rowScale,
    const float* __restrict__ B, int ldb,
    const float* __restrict__ bias,
    float* __restrict__ C, int ldc,
    int M, int Ncols, int K, int relu)
{
    __shared__ __align__(16) __nv_bfloat16 Ah[GBM * ASTR];
    __shared__ __align__(16) __nv_bfloat16 Al[GBM * ASTR];
    __shared__ __align__(16) __nv_bfloat16 Bh[GBK * BSTR];
    __shared__ __align__(16) __nv_bfloat16 Bl[GBK * BSTR];

    const int t = threadIdx.x;
    const int wid = t >> 5;
    const int lane = t & 31;
    const int warp_m = wid >> 1;     // 0..3 -> 32-row strips
    const int warp_n = wid & 1;      // 0..1 -> 32-col strips
    const int m0 = blockIdx.y * GBM;
    const int n0 = blockIdx.x * GBN;

    // per-thread rowScale cache for the 4 A rows this thread loads
    float acc[2][4][4];
    #pragma unroll
    for (int mi = 0; mi < 2; mi++)
        #pragma unroll
        for (int ni = 0; ni < 4; ni++)
            #pragma unroll
            for (int j = 0; j < 4; j++) acc[mi][ni][j] = 0.f;

    const uint32_t sAh = (uint32_t)__cvta_generic_to_shared(Ah);
    const uint32_t sAl = (uint32_t)__cvta_generic_to_shared(Al);
    const uint32_t sBh = (uint32_t)__cvta_generic_to_shared(Bh);
    const uint32_t sBl = (uint32_t)__cvta_generic_to_shared(Bl);

    // ldmatrix lane addressing (halves): pattern shared by A (direct) and B (trans)
    const int lrow = lane & 15;
    const int lcol8 = (lane >> 4) << 3;

    const int nK = (K + GBK - 1) / GBK;
    for (int kt = 0; kt < nK; kt++) {
        const int k0 = kt * GBK;

        // ---- load A tile: 128 rows x 8 float4-slots = 1024 slots ----
        #pragma unroll
        for (int i = 0; i < 4; i++) {
            int slot = t + 256 * i;
            int r = slot >> 3;
            int kv = slot & 7;
            int grow = m0 + r;
            int gk = k0 + kv * 4;
            float4 v = make_float4(0.f, 0.f, 0.f, 0.f);
            if (grow < M && gk < K)
                v = *(const float4*)(A + (size_t)grow * lda + gk);
            if (rowScale != nullptr && grow < M) {
                float s = rowScale[grow];
                v.x *= s; v.y *= s; v.z *= s; v.w *= s;
            }
            __nv_bfloat16 h0 = __float2bfloat16(v.x);
            __nv_bfloat16 h1 = __float2bfloat16(v.y);
            __nv_bfloat16 h2 = __float2bfloat16(v.z);
            __nv_bfloat16 h3 = __float2bfloat16(v.w);
            __nv_bfloat16 l0 = __float2bfloat16(v.x - __bfloat162float(h0));
            __nv_bfloat16 l1 = __float2bfloat16(v.y - __bfloat162float(h1));
            __nv_bfloat16 l2 = __float2bfloat16(v.z - __bfloat162float(h2));
            __nv_bfloat16 l3 = __float2bfloat16(v.w - __bfloat162float(h3));
            int off = r * ASTR + kv * 4;
            __nv_bfloat162* ph = (__nv_bfloat162*)&Ah[off];
            ph[0] = __nv_bfloat162(h0, h1); ph[1] = __nv_bfloat162(h2, h3);
            __nv_bfloat162* pl = (__nv_bfloat162*)&Al[off];
            pl[0] = __nv_bfloat162(l0, l1); pl[1] = __nv_bfloat162(l2, l3);
        }

        // ---- load B tile: 32 rows x 16 float4-slots = 512 slots ----
        #pragma unroll
        for (int i = 0; i < 2; i++) {
            int slot = t + 256 * i;
            int r = slot >> 4;
            int nv = slot & 15;
            int gk = k0 + r;
            int gc = n0 + nv * 4;
            float4 v = make_float4(0.f, 0.f, 0.f, 0.f);
            if (gk < K && gc < Ncols)
                v = *(const float4*)(B + (size_t)gk * ldb + gc);
            __nv_bfloat16 h0 = __float2bfloat16(v.x);
            __nv_bfloat16 h1 = __float2bfloat16(v.y);
            __nv_bfloat16 h2 = __float2bfloat16(v.z);
            __nv_bfloat16 h3 = __float2bfloat16(v.w);
            __nv_bfloat16 l0 = __float2bfloat16(v.x - __bfloat162float(h0));
            __nv_bfloat16 l1 = __float2bfloat16(v.y - __bfloat162float(h1));
            __nv_bfloat16 l2 = __float2bfloat16(v.z - __bfloat162float(h2));
            __nv_bfloat16 l3 = __float2bfloat16(v.w - __bfloat162float(h3));
            int off = r * BSTR + nv * 4;
            __nv_bfloat162* ph = (__nv_bfloat162*)&Bh[off];
            ph[0] = __nv_bfloat162(h0, h1); ph[1] = __nv_bfloat162(h2, h3);
            __nv_bfloat162* pl = (__nv_bfloat162*)&Bl[off];
            pl[0] = __nv_bfloat162(l0, l1); pl[1] = __nv_bfloat162(l2, l3);
        }

        __syncthreads();

        // ---- compute: 2 k-steps of 16 ----
        #pragma unroll
        for (int ks = 0; ks < 2; ks++) {
            uint32_t ah[2][4], al[2][4];
            #pragma unroll
            for (int mi = 0; mi < 2; mi++) {
                int row = warp_m * 32 + mi * 16 + lrow;
                int col = ks * 16 + lcol8;
                uint32_t off = (uint32_t)(row * ASTR + col) * 2u;
                ldsm_x4(ah[mi][0], ah[mi][1], ah[mi][2], ah[mi][3], sAh + off);
                ldsm_x4(al[mi][0], al[mi][1], al[mi][2], al[mi][3], sAl + off);
            }
            uint32_t bh[4][2], bl[4][2];
            #pragma unroll
            for (int nj = 0; nj < 2; nj++) {
                int row = ks * 16 + lrow;
                int col = warp_n * 32 + nj * 16 + lcol8;
                uint32_t off = (uint32_t)(row * BSTR + col) * 2u;
                uint32_t r0, r1, r2, r3;
                ldsm_x4_t(r0, r1, r2, r3, sBh + off);
                bh[nj * 2 + 0][0] = r0; bh[nj * 2 + 0][1] = r1;
                bh[nj * 2 + 1][0] = r2; bh[nj * 2 + 1][1] = r3;
                ldsm_x4_t(r0, r1, r2, r3, sBl + off);
                bl[nj * 2 + 0][0] = r0; bl[nj * 2 + 0][1] = r1;
                bl[nj * 2 + 1][0] = r2; bl[nj * 2 + 1][1] = r3;
            }
            #pragma unroll
            for (int mi = 0; mi < 2; mi++)
                #pragma unroll
                for (int ni = 0; ni < 4; ni++) {
                    mma_bf16(acc[mi][ni], ah[mi], bh[ni]);
                    mma_bf16(acc[mi][ni], ah[mi], bl[ni]);
                    mma_bf16(acc[mi][ni], al[mi], bh[ni]);
                }
        }
        __syncthreads();
    }

    // ---- epilogue: bias (+relu), float2 stores ----
    const int g = lane >> 2;
    const int tig = lane & 3;
    #pragma unroll
    for (int mi = 0; mi < 2; mi++) {
        #pragma unroll
        for (int ni = 0; ni < 4; ni++) {
            int col = n0 + warp_n * 32 + ni * 8 + tig * 2;
            if (col >= Ncols) continue;
            float bx = bias[col], by = bias[col + 1];
            int row0 = m0 + warp_m * 32 + mi * 16 + g;
            if (row0 < M) {
                float vx = acc[mi][ni][0] + bx;
                float vy = acc[mi][ni][1] + by;
                if (relu) { vx = fmaxf(vx, 0.f); vy = fmaxf(vy, 0.f); }
                *(float2*)(C + (size_t)row0 * ldc + col) = make_float2(vx, vy);
            }
            int row1 = row0 + 8;
            if (row1 < M) {
                float vx = acc[mi][ni][2] + bx;
                float vy = acc[mi][ni][3] + by;
                if (relu) { vx = fmaxf(vx, 0.f); vy = fmaxf(vy, 0.f); }
                *(float2*)(C + (size_t)row1 * ldc + col) = make_float2(vx, vy);
            }
        }
    }
}

// ---------------- LayerNorm (one warp per row of DD=300 cols) ---------------
__global__ void ln_kernel(float* __restrict__ X, int ld,
                          const float* __restrict__ gamma,
                          const float* __restrict__ beta, int M) {
    int warp = (int)((blockIdx.x * (long)blockDim.x + threadIdx.x) >> 5);
    int lane = threadIdx.x & 31;
    if (warp >= M) return;
    float* p = X + (size_t)warp * ld;

    float v[10];
    float sum = 0.f;
    #pragma unroll
    for (int k = 0; k < 10; k++) {
        int c = lane + 32 * k;
        v[k] = (c < DD) ? p[c] : 0.f;
        sum += v[k];
    }
    #pragma unroll
    for (int o = 16; o > 0; o >>= 1) sum += __shfl_xor_sync(0xFFFFFFFFu, sum, o);
    float mu = sum * (1.f / DD);

    float var = 0.f;
    #pragma unroll
    for (int k = 0; k < 10; k++) {
        int c = lane + 32 * k;
        float d = (c < DD) ? (v[k] - mu) : 0.f;
        var += d * d;
    }
    #pragma unroll
    for (int o = 16; o > 0; o >>= 1) var += __shfl_xor_sync(0xFFFFFFFFu, var, o);
    float rsig = rsqrtf(var * (1.f / DD) + 1e-5f);

    #pragma unroll
    for (int k = 0; k < 10; k++) {
        int c = lane + 32 * k;
        if (c < DD) p[c] = (v[k] - mu) * rsig * gamma[c] + beta[c];
    }
}

// ---------------- launch ----------------------------------------------------
extern "C" void kernel_launch(void* const* d_in, const int* in_sizes, int n_in,
                              void* d_out, int out_size) {
    const float* x    = (const float*)d_in[0];
    const int*   er   = (const int*)d_in[1];
    const int*   ec   = (const int*)d_in[2];
    const float* Wr   = (const float*)d_in[3];
    const float* br   = (const float*)d_in[4];
    const float* Wc   = (const float*)d_in[5];
    const float* bc   = (const float*)d_in[6];
    const float* Wrs  = (const float*)d_in[7];
    const float* brs  = (const float*)d_in[8];
    const float* g_rs = (const float*)d_in[9];
    const float* b_rs = (const float*)d_in[10];
    const float* Wcs  = (const float*)d_in[11];
    const float* bcs  = (const float*)d_in[12];
    const float* g_cs = (const float*)d_in[13];
    const float* b_cs = (const float*)d_in[14];
    const float* Wm   = (const float*)d_in[15];
    const float* bm   = (const float*)d_in[16];
    const float* g_m  = (const float*)d_in[17];
    const float* b_m  = (const float*)d_in[18];
    float* out = (float*)d_out;

    float *deg, *aggr, *aggc, *rowg, *colg, *merged;
    cudaGetSymbolAddress((void**)&deg,    g_deg);
    cudaGetSymbolAddress((void**)&aggr,   g_agg_r);
    cudaGetSymbolAddress((void**)&aggc,   g_agg_c);
    cudaGetSymbolAddress((void**)&rowg,   g_rowg);
    cudaGetSymbolAddress((void**)&colg,   g_colg);
    cudaGetSymbolAddress((void**)&merged, g_merged);

    // zero degree + aggregation buffers
    zero_kernel<<<1024, 256>>>((float4*)deg, (long)(4 * NN) / 4);
    zero_kernel<<<29297, 256>>>((float4*)aggr, (long)NN * DV);
    zero_kernel<<<29297, 256>>>((float4*)aggc, (long)NN * DV);

    // degrees -> rsqrt norms
    degree_kernel<<<(NE + 255) / 256, 256>>>(er, ec);
    norm_kernel<<<(4 * NN + 255) / 256, 256>>>();

    // edge scatter (agg[dst] += x[src]*norm_src[src])
    long sw = (long)NE * DV;
    int sgrid = (int)((sw + 255) / 256);
    scatter_kernel<<<sgrid, 256>>>(er, er + NE, deg + 0 * NN, (const float4*)x, (float4*)aggr);
    scatter_kernel<<<sgrid, 256>>>(ec, ec + NE, deg + 2 * NN, (const float4*)x, (float4*)aggc);

    dim3 ggrid((DD + GBN - 1) / GBN, (NN + GBM - 1) / GBM);

    // GraphConv GEMMs: relu((agg * norm_dst) @ W + b)
    gemm_tc_kernel<<<ggrid, 256>>>(aggr, DD, deg + 1 * NN, Wr, DD, br, rowg, DD, NN, DD, DD, 1);
    gemm_tc_kernel<<<ggrid, 256>>>(aggc, DD, deg + 3 * NN, Wc, DD, bc, colg, DD, NN, DD, DD, 1);

    // support GEMMs into merged buffer halves, then LayerNorm in place
    gemm_tc_kernel<<<ggrid, 256>>>(rowg, DD, nullptr, Wrs, DD, brs, merged,      2 * DD, NN, DD, DD, 0);
    gemm_tc_kernel<<<ggrid, 256>>>(colg, DD, nullptr, Wcs, DD, bcs, merged + DD, 2 * DD, NN, DD, DD, 0);
    int lngrid = (NN + 7) / 8;
    ln_kernel<<<lngrid, 256>>>(merged,      2 * DD, g_rs, b_rs, NN);
    ln_kernel<<<lngrid, 256>>>(merged + DD, 2 * DD, g_cs, b_cs, NN);

    // merge GEMM (K=600) + final LayerNorm into output
    gemm_tc_kernel<<<ggrid, 256>>>(merged, 2 * DD, nullptr, Wm, DD, bm, out, DD, NN, DD, 2 * DD, 0);
    ln_kernel<<<lngrid, 256>>>(out, DD, g_m, b_m, NN);
}

// round 3
// speedup vs baseline: 1.9468x; 1.1757x over previous
#include <cuda_runtime.h>
#include <cuda_bf16.h>
#include <cstddef>
#include <cstdint>

#define NN 100000
#define NE 1000000
#define DD 300
#define DV 75          // float4 per fp32 row
#define MP 100096      // NN padded to 128
#define KP1 320        // K=300 padded to 32
#define NP  320        // N=300 padded to 64
#define KP2 640        // K=600 padded

typedef __nv_bfloat16 bf16;
typedef __nv_bfloat162 bf162;

// ---------------- scratch (device globals; no allocation allowed) ----------
__device__ __align__(16) float g_deg[4 * NN];
__device__ __align__(16) float g_agg_r[(size_t)NN * DD];
__device__ __align__(16) float g_agg_c[(size_t)NN * DD];
__device__ __align__(16) float g_merged[(size_t)NN * 2 * DD];

// bf16 hi/lo operand planes (padded)
__device__ __align__(16) bf16 g_aggr_h[(size_t)MP * KP1];
__device__ __align__(16) bf16 g_aggr_l[(size_t)MP * KP1];
__device__ __align__(16) bf16 g_aggc_h[(size_t)MP * KP1];
__device__ __align__(16) bf16 g_aggc_l[(size_t)MP * KP1];
__device__ __align__(16) bf16 g_rowg_h[(size_t)MP * KP1];
__device__ __align__(16) bf16 g_rowg_l[(size_t)MP * KP1];
__device__ __align__(16) bf16 g_colg_h[(size_t)MP * KP1];
__device__ __align__(16) bf16 g_colg_l[(size_t)MP * KP1];
__device__ __align__(16) bf16 g_mrg_h[(size_t)MP * KP2];
__device__ __align__(16) bf16 g_mrg_l[(size_t)MP * KP2];
// weight planes
__device__ __align__(16) bf16 g_Wr_h[KP1 * NP],  g_Wr_l[KP1 * NP];
__device__ __align__(16) bf16 g_Wc_h[KP1 * NP],  g_Wc_l[KP1 * NP];
__device__ __align__(16) bf16 g_Wrs_h[KP1 * NP], g_Wrs_l[KP1 * NP];
__device__ __align__(16) bf16 g_Wcs_h[KP1 * NP], g_Wcs_l[KP1 * NP];
__device__ __align__(16) bf16 g_Wm_h[KP2 * NP],  g_Wm_l[KP2 * NP];

// ---------------- helpers ----------------------------------------------------
__device__ __forceinline__ void split_bf16(float v, bf16& h, bf16& l) {
    h = __float2bfloat16(v);
    l = __float2bfloat16(v - __bfloat162float(h));
}

// ---------------- zero ------------------------------------------------------
__global__ void zero_kernel(float4* __restrict__ p, long n4) {
    long i = (long)blockIdx.x * blockDim.x + threadIdx.x;
    long stride = (long)gridDim.x * blockDim.x;
    float4 z = make_float4(0.f, 0.f, 0.f, 0.f);
    for (; i < n4; i += stride) p[i] = z;
}

// zero tail rows [NN, MP) of merged planes
__global__ void zero_mrg_tail_kernel() {
    long n = (long)(MP - NN) * KP2;   // per plane
    long i = (long)blockIdx.x * blockDim.x + threadIdx.x;
    long stride = (long)gridDim.x * blockDim.x;
    bf16 z = __float2bfloat16(0.f);
    for (; i < 2 * n; i += stride) {
        if (i < n) g_mrg_h[(size_t)NN * KP2 + i] = z;
        else       g_mrg_l[(size_t)NN * KP2 + (i - n)] = z;
    }
}

// ---------------- degrees ---------------------------------------------------
__global__ void degree_kernel(const int* __restrict__ er, const int* __restrict__ ec) {
    int i = blockIdx.x * blockDim.x + threadIdx.x;
    if (i < NE) {
        atomicAdd(&g_deg[0 * NN + er[i]],      1.f);
        atomicAdd(&g_deg[1 * NN + er[NE + i]], 1.f);
        atomicAdd(&g_deg[2 * NN + ec[i]],      1.f);
        atomicAdd(&g_deg[3 * NN + ec[NE + i]], 1.f);
    }
}

__global__ void norm_kernel() {
    int i = blockIdx.x * blockDim.x + threadIdx.x;
    if (i < 4 * NN) {
        float d = g_deg[i];
        g_deg[i] = (d > 0.f) ? rsqrtf(d) : 0.f;
    }
}

// ---------------- edge scatter:  agg[dst] += x[src] * norm_src[src] ---------
__global__ void scatter_kernel(const int* __restrict__ src, const int* __restrict__ dst,
                               const float* __restrict__ nsrc,
                               const float4* __restrict__ x, float4* __restrict__ agg) {
    long i = (long)blockIdx.x * blockDim.x + threadIdx.x;
    if (i >= (long)NE * DV) return;
    int e = (int)(i / DV);
    int c = (int)(i - (long)e * DV);
    int s = src[e];
    int d = dst[e];
    float ns = nsrc[s];
    float4 v = x[(size_t)s * DV + c];
    float4* p = &agg[(size_t)d * DV + c];
    asm volatile("red.global.add.v4.f32 [%0], {%1, %2, %3, %4};"
                 :: "l"(p), "f"(v.x * ns), "f"(v.y * ns), "f"(v.z * ns), "f"(v.w * ns)
                 : "memory");
}

// ---------------- converts ---------------------------------------------------
// agg (fp32, NN x 300) * norm_dst -> hi/lo planes (MP x KP1), zero padded
__global__ void agg_convert_kernel(const float4* __restrict__ agg,
                                   const float* __restrict__ ndst,
                                   bf16* __restrict__ Ah, bf16* __restrict__ Al) {
    long idx = (long)blockIdx.x * blockDim.x + threadIdx.x;
    if (idx >= (long)MP * (KP1 / 4)) return;
    int row = (int)(idx / (KP1 / 4));
    int kq  = (int)(idx - (long)row * (KP1 / 4));
    float4 v = make_float4(0.f, 0.f, 0.f, 0.f);
    if (row < NN && kq < DV) {
        v = agg[(size_t)row * DV + kq];
        float s = ndst[row];
        v.x *= s; v.y *= s; v.z *= s; v.w *= s;
    }
    bf16 h0, h1, h2, h3, l0, l1, l2, l3;
    split_bf16(v.x, h0, l0); split_bf16(v.y, h1, l1);
    split_bf16(v.z, h2, l2); split_bf16(v.w, h3, l3);
    size_t off = (size_t)row * KP1 + kq * 4;
    *(bf162*)&Ah[off]     = bf162(h0, h1);
    *(bf162*)&Ah[off + 2] = bf162(h2, h3);
    *(bf162*)&Al[off]     = bf162(l0, l1);
    *(bf162*)&Al[off + 2] = bf162(l2, l3);
}

// weight (K x Ncols fp32) -> hi/lo planes (KPp x NP), zero padded
__global__ void w_convert_kernel(const float* __restrict__ W, int K, int Ncols, int KPp,
                                 bf16* __restrict__ Wh, bf16* __restrict__ Wl) {
    int idx = blockIdx.x * blockDim.x + threadIdx.x;
    if (idx >= KPp * NP) return;
    int k = idx / NP;
    int n = idx - k * NP;
    float v = (k < K && n < Ncols) ? W[(size_t)k * Ncols + n] : 0.f;
    bf16 h, l;
    split_bf16(v, h, l);
    Wh[idx] = h; Wl[idx] = l;
}

// ================= Tensor-core GEMM (pre-split bf16 planes) =================
#define GBM 128
#define GBN 64
#define GBK 32
#define ASTR 40            // halves per A smem row (32 + 8 pad)
#define BSTR 72            // halves per B smem row (64 + 8 pad)
#define A_STAGE_B (GBM * ASTR * 2)   // 10240 bytes
#define B_STAGE_B (GBK * BSTR * 2)   // 4608 bytes
#define SMEM_TOTAL (2 * (2 * A_STAGE_B + 2 * B_STAGE_B))  // 59392

__device__ __forceinline__ void ldsm_x4(uint32_t& r0, uint32_t& r1, uint32_t& r2, uint32_t& r3,
                                        uint32_t addr) {
    asm volatile("ldmatrix.sync.aligned.m8n8.x4.shared.b16 {%0,%1,%2,%3}, [%4];"
                 : "=r"(r0), "=r"(r1), "=r"(r2), "=r"(r3) : "r"(addr));
}
__device__ __forceinline__ void ldsm_x4_t(uint32_t& r0, uint32_t& r1, uint32_t& r2, uint32_t& r3,
                                          uint32_t addr) {
    asm volatile("ldmatrix.sync.aligned.m8n8.x4.trans.shared.b16 {%0,%1,%2,%3}, [%4];"
                 : "=r"(r0), "=r"(r1), "=r"(r2), "=r"(r3) : "r"(addr));
}
__device__ __forceinline__ void mma_bf16(float* c, const uint32_t* a, const uint32_t* b) {
    asm volatile("mma.sync.aligned.m16n8k16.row.col.f32.bf16.bf16.f32 "
                 "{%0,%1,%2,%3}, {%4,%5,%6,%7}, {%8,%9}, {%0,%1,%2,%3};"
                 : "+f"(c[0]), "+f"(c[1]), "+f"(c[2]), "+f"(c[3])
                 : "r"(a[0]), "r"(a[1]), "r"(a[2]), "r"(a[3]), "r"(b[0]), "r"(b[1]));
}
__device__ __forceinline__ void cp16(uint32_t dst, const void* src) {
    asm volatile("cp.async.cg.shared.global [%0], [%1], 16;" :: "r"(dst), "l"(src));
}

// mode 0: fp32 out (bias, optional relu), guards row<M col<Ncols
// mode 1: bf16 hi/lo plane out (bias+relu), writes full padded tile with zeros OOB
__global__ __launch_bounds__(256) void gemm_tc2_kernel(
    const bf16* __restrict__ Aph, const bf16* __restrict__ Apl, int lda,
    const bf16* __restrict__ Bph, const bf16* __restrict__ Bpl,
    const float* __restrict__ bias,
    int M, int Ncols, int nK, int mode, int relu,
    float* __restrict__ Cf, int ldc,
    bf16* __restrict__ Ch, bf16* __restrict__ Cl, int ldcp)
{
    extern __shared__ __align__(16) char smem[];
    const uint32_t sAh = (uint32_t)__cvta_generic_to_shared(smem);
    const uint32_t sAl = sAh + 2 * A_STAGE_B;
    const uint32_t sBh = sAl + 2 * A_STAGE_B;
    const uint32_t sBl = sBh + 2 * B_STAGE_B;

    const int t = threadIdx.x;
    const int wid = t >> 5;
    const int lane = t & 31;
    const int warp_m = wid >> 1;
    const int warp_n = wid & 1;
    const int m0 = blockIdx.y * GBM;
    const int n0 = blockIdx.x * GBN;

    float acc[2][4][4];
    #pragma unroll
    for (int mi = 0; mi < 2; mi++)
        #pragma unroll
        for (int ni = 0; ni < 4; ni++)
            #pragma unroll
            for (int j = 0; j < 4; j++) acc[mi][ni][j] = 0.f;

    // loader indices
    const int ar = t >> 2;            // A: 128 rows, 4 chunks each (per 256-slot pass)
    const int ac = t & 3;
    const int br = t >> 3;            // B: 32 rows, 8 chunks
    const int bc = t & 7;

    // issue one stage of cp.async
    auto load_stage = [&](int stage, int k0) {
        uint32_t asoff = (uint32_t)stage * A_STAGE_B;
        uint32_t bsoff = (uint32_t)stage * B_STAGE_B;
        #pragma unroll
        for (int i = 0; i < 2; i++) {
            int r = ar + i * 64;      // slots t and t+256 -> rows split
            uint32_t d = asoff + (uint32_t)(r * ASTR + ac * 8) * 2;
            size_t s = (size_t)(m0 + r) * lda + k0 + ac * 8;
            cp16(sAh + d, Aph + s);
            cp16(sAl + d, Apl + s);
        }
        {
            uint32_t d = bsoff + (uint32_t)(br * BSTR + bc * 8) * 2;
            size_t s = (size_t)(k0 + br) * NP + n0 + bc * 8;
            cp16(sBh + d, Bph + s);
            cp16(sBl + d, Bpl + s);
        }
        asm volatile("cp.async.commit_group;");
    };

    load_stage(0, 0);

    const int lrow = lane & 15;
    const int lcol8 = (lane >> 4) << 3;

    for (int kt = 0; kt < nK; kt++) {
        if (kt + 1 < nK) {
            load_stage((kt + 1) & 1, (kt + 1) * GBK);
            asm volatile("cp.async.wait_group 1;");
        } else {
            asm volatile("cp.async.wait_group 0;");
        }
        __syncthreads();

        const int stage = kt & 1;
        const uint32_t aoff = (uint32_t)stage * A_STAGE_B;
        const uint32_t boff = (uint32_t)stage * B_STAGE_B;

        #pragma unroll
        for (int ks = 0; ks < 2; ks++) {
            uint32_t ah[2][4], al[2][4];
            #pragma unroll
            for (int mi = 0; mi < 2; mi++) {
                int row = warp_m * 32 + mi * 16 + lrow;
                int col = ks * 16 + lcol8;
                uint32_t off = aoff + (uint32_t)(row * ASTR + col) * 2;
                ldsm_x4(ah[mi][0], ah[mi][1], ah[mi][2], ah[mi][3], sAh + off);
                ldsm_x4(al[mi][0], al[mi][1], al[mi][2], al[mi][3], sAl + off);
            }
            uint32_t bh[4][2], bl[4][2];
            #pragma unroll
            for (int nj = 0; nj < 2; nj++) {
                int row = ks * 16 + lrow;
                int col = warp_n * 32 + nj * 16 + lcol8;
                uint32_t off = boff + (uint32_t)(row * BSTR + col) * 2;
                uint32_t r0, r1, r2, r3;
                ldsm_x4_t(r0, r1, r2, r3, sBh + off);
                bh[nj * 2 + 0][0] = r0; bh[nj * 2 + 0][1] = r1;
                bh[nj * 2 + 1][0] = r2; bh[nj * 2 + 1][1] = r3;
                ldsm_x4_t(r0, r1, r2, r3, sBl + off);
                bl[nj * 2 + 0][0] = r0; bl[nj * 2 + 0][1] = r1;
                bl[nj * 2 + 1][0] = r2; bl[nj * 2 + 1][1] = r3;
            }
            #pragma unroll
            for (int mi = 0; mi < 2; mi++)
                #pragma unroll
                for (int ni = 0; ni < 4; ni++) {
                    mma_bf16(acc[mi][ni], ah[mi], bh[ni]);
                    mma_bf16(acc[mi][ni], ah[mi], bl[ni]);
                    mma_bf16(acc[mi][ni], al[mi], bh[ni]);
                }
        }
        __syncthreads();
    }

    // ---- epilogue ----
    const int g = lane >> 2;
    const int tig = lane & 3;
    #pragma unroll
    for (int mi = 0; mi < 2; mi++) {
        #pragma unroll
        for (int ni = 0; ni < 4; ni++) {
            int col = n0 + warp_n * 32 + ni * 8 + tig * 2;
            float bx = (col     < Ncols) ? bias[col]     : 0.f;
            float by = (col + 1 < Ncols) ? bias[col + 1] : 0.f;
            #pragma unroll
            for (int rr = 0; rr < 2; rr++) {
                int row = m0 + warp_m * 32 + mi * 16 + g + rr * 8;
                float vx = acc[mi][ni][rr * 2 + 0] + bx;
                float vy = acc[mi][ni][rr * 2 + 1] + by;
                if (relu) { vx = fmaxf(vx, 0.f); vy = fmaxf(vy, 0.f); }
                if (mode == 0) {
                    if (row < M && col < Ncols)
                        *(float2*)(Cf + (size_t)row * ldc + col) = make_float2(vx, vy);
                } else {
                    bool ok = (row < M) && (col < Ncols);
                    if (!ok) { vx = 0.f; vy = 0.f; }
                    bool oky = ok && (col + 1 < Ncols);
                    if (!oky) vy = 0.f;
                    bf16 hx, lx, hy, ly;
                    split_bf16(vx, hx, lx);
                    split_bf16(vy, hy, ly);
                    size_t o = (size_t)row * ldcp + col;
                    *(bf162*)&Ch[o] = bf162(hx, hy);
                    *(bf162*)&Cl[o] = bf162(lx, ly);
                }
            }
        }
    }
}

// ---------------- LayerNorm (fp32, in place) --------------------------------
__global__ void ln_kernel(float* __restrict__ X, int ld,
                          const float* __restrict__ gamma,
                          const float* __restrict__ beta, int M) {
    int warp = (int)((blockIdx.x * (long)blockDim.x + threadIdx.x) >> 5);
    int lane = threadIdx.x & 31;
    if (warp >= M) return;
    float* p = X + (size_t)warp * ld;

    float v[10];
    float sum = 0.f;
    #pragma unroll
    for (int k = 0; k < 10; k++) {
        int c = lane + 32 * k;
        v[k] = (c < DD) ? p[c] : 0.f;
        sum += v[k];
    }
    #pragma unroll
    for (int o = 16; o > 0; o >>= 1) sum += __shfl_xor_sync(0xFFFFFFFFu, sum, o);
    float mu = sum * (1.f / DD);
    float var = 0.f;
    #pragma unroll
    for (int k = 0; k < 10; k++) {
        int c = lane + 32 * k;
        float d = (c < DD) ? (v[k] - mu) : 0.f;
        var += d * d;
    }
    #pragma unroll
    for (int o = 16; o > 0; o >>= 1) var += __shfl_xor_sync(0xFFFFFFFFu, var, o);
    float rsig = rsqrtf(var * (1.f / DD) + 1e-5f);
    #pragma unroll
    for (int k = 0; k < 10; k++) {
        int c = lane + 32 * k;
        if (c < DD) p[c] = (v[k] - mu) * rsig * gamma[c] + beta[c];
    }
}

// LN both halves of merged row (fp32 in) -> bf16 hi/lo planes (MP x KP2)
__global__ void ln_merged_kernel(const float* __restrict__ merged,
                                 const float* __restrict__ g0, const float* __restrict__ b0,
                                 const float* __restrict__ g1, const float* __restrict__ b1) {
    int warp = (int)((blockIdx.x * (long)blockDim.x + threadIdx.x) >> 5);
    int lane = threadIdx.x & 31;
    if (warp >= NN) return;
    const float* prow = merged + (size_t)warp * (2 * DD);
    size_t orow = (size_t)warp * KP2;

    #pragma unroll
    for (int half = 0; half < 2; half++) {
        const float* p = prow + half * DD;
        const float* gamma = half ? g1 : g0;
        const float* beta  = half ? b1 : b0;
        float v[10];
        float sum = 0.f;
        #pragma unroll
        for (int k = 0; k < 10; k++) {
            int c = lane + 32 * k;
            v[k] = (c < DD) ? p[c] : 0.f;
            sum += v[k];
        }
        #pragma unroll
        for (int o = 16; o > 0; o >>= 1) sum += __shfl_xor_sync(0xFFFFFFFFu, sum, o);
        float mu = sum * (1.f / DD);
        float var = 0.f;
        #pragma unroll
        for (int k = 0; k < 10; k++) {
            int c = lane + 32 * k;
            float d = (c < DD) ? (v[k] - mu) : 0.f;
            var += d * d;
        }
        #pragma unroll
        for (int o = 16; o > 0; o >>= 1) var += __shfl_xor_sync(0xFFFFFFFFu, var, o);
        float rsig = rsqrtf(var * (1.f / DD) + 1e-5f);
        #pragma unroll
        for (int k = 0; k < 10; k++) {
            int c = lane + 32 * k;
            if (c < DD) {
                float w = (v[k] - mu) * rsig * gamma[c] + beta[c];
                bf16 h, l;
                split_bf16(w, h, l);
                g_mrg_h[orow + half * DD + c] = h;
                g_mrg_l[orow + half * DD + c] = l;
            }
        }
    }
    // zero pad cols [600, 640)
    bf16 z = __float2bfloat16(0.f);
    g_mrg_h[orow + 600 + lane] = z;
    g_mrg_l[orow + 600 + lane] = z;
    if (lane < 8) {
        g_mrg_h[orow + 632 + lane] = z;
        g_mrg_l[orow + 632 + lane] = z;
    }
}

// ---------------- launch ----------------------------------------------------
extern "C" void kernel_launch(void* const* d_in, const int* in_sizes, int n_in,
                              void* d_out, int out_size) {
    const float* x    = (const float*)d_in[0];
    const int*   er   = (const int*)d_in[1];
    const int*   ec   = (const int*)d_in[2];
    const float* Wr   = (const float*)d_in[3];
    const float* br   = (const float*)d_in[4];
    const float* Wc   = (const float*)d_in[5];
    const float* bc   = (const float*)d_in[6];
    const float* Wrs  = (const float*)d_in[7];
    const float* brs  = (const float*)d_in[8];
    const float* g_rs = (const float*)d_in[9];
    const float* b_rs = (const float*)d_in[10];
    const float* Wcs  = (const float*)d_in[11];
    const float* bcs  = (const float*)d_in[12];
    const float* g_cs = (const float*)d_in[13];
    const float* b_cs = (const float*)d_in[14];
    const float* Wm   = (const float*)d_in[15];
    const float* bm   = (const float*)d_in[16];
    const float* g_m  = (const float*)d_in[17];
    const float* b_m  = (const float*)d_in[18];
    float* out = (float*)d_out;

    float *deg, *aggr, *aggc, *merged;
    cudaGetSymbolAddress((void**)&deg,    g_deg);
    cudaGetSymbolAddress((void**)&aggr,   g_agg_r);
    cudaGetSymbolAddress((void**)&aggc,   g_agg_c);
    cudaGetSymbolAddress((void**)&merged, g_merged);

    bf16 *aggr_h, *aggr_l, *aggc_h, *aggc_l, *rowg_h, *rowg_l, *colg_h, *colg_l;
    bf16 *mrg_h, *mrg_l;
    bf16 *Wr_h, *Wr_l, *Wc_h, *Wc_l, *Wrs_h, *Wrs_l, *Wcs_h, *Wcs_l, *Wm_h, *Wm_l;
    cudaGetSymbolAddress((void**)&aggr_h, g_aggr_h);
    cudaGetSymbolAddress((void**)&aggr_l, g_aggr_l);
    cudaGetSymbolAddress((void**)&aggc_h, g_aggc_h);
    cudaGetSymbolAddress((void**)&aggc_l, g_aggc_l);
    cudaGetSymbolAddress((void**)&rowg_h, g_rowg_h);
    cudaGetSymbolAddress((void**)&rowg_l, g_rowg_l);
    cudaGetSymbolAddress((void**)&colg_h, g_colg_h);
    cudaGetSymbolAddress((void**)&colg_l, g_colg_l);
    cudaGetSymbolAddress((void**)&mrg_h,  g_mrg_h);
    cudaGetSymbolAddress((void**)&mrg_l,  g_mrg_l);
    cudaGetSymbolAddress((void**)&Wr_h,  g_Wr_h);   cudaGetSymbolAddress((void**)&Wr_l,  g_Wr_l);
    cudaGetSymbolAddress((void**)&Wc_h,  g_Wc_h);   cudaGetSymbolAddress((void**)&Wc_l,  g_Wc_l);
    cudaGetSymbolAddress((void**)&Wrs_h, g_Wrs_h);  cudaGetSymbolAddress((void**)&Wrs_l, g_Wrs_l);
    cudaGetSymbolAddress((void**)&Wcs_h, g_Wcs_h);  cudaGetSymbolAddress((void**)&Wcs_l, g_Wcs_l);
    cudaGetSymbolAddress((void**)&Wm_h,  g_Wm_h);   cudaGetSymbolAddress((void**)&Wm_l,  g_Wm_l);

    cudaFuncSetAttribute(gemm_tc2_kernel,
                         cudaFuncAttributeMaxDynamicSharedMemorySize, SMEM_TOTAL);

    // zero degree + aggregation buffers
    zero_kernel<<<1024, 256>>>((float4*)deg, (long)(4 * NN) / 4);
    zero_kernel<<<29297, 256>>>((float4*)aggr, (long)NN * DV);
    zero_kernel<<<29297, 256>>>((float4*)aggc, (long)NN * DV);

    // weight splits (independent of graph work)
    w_convert_kernel<<<(KP1 * NP + 255) / 256, 256>>>(Wr,  DD, DD, KP1, Wr_h,  Wr_l);
    w_convert_kernel<<<(KP1 * NP + 255) / 256, 256>>>(Wc,  DD, DD, KP1, Wc_h,  Wc_l);
    w_convert_kernel<<<(KP1 * NP + 255) / 256, 256>>>(Wrs, DD, DD, KP1, Wrs_h, Wrs_l);
    w_convert_kernel<<<(KP1 * NP + 255) / 256, 256>>>(Wcs, DD, DD, KP1, Wcs_h, Wcs_l);
    w_convert_kernel<<<(KP2 * NP + 255) / 256, 256>>>(Wm, 2 * DD, DD, KP2, Wm_h, Wm_l);

    // degrees -> rsqrt norms
    degree_kernel<<<(NE + 255) / 256, 256>>>(er, ec);
    norm_kernel<<<(4 * NN + 255) / 256, 256>>>();

    // edge scatter
    long sw = (long)NE * DV;
    int sgrid = (int)((sw + 255) / 256);
    scatter_kernel<<<sgrid, 256>>>(er, er + NE, deg + 0 * NN, (const float4*)x, (float4*)aggr);
    scatter_kernel<<<sgrid, 256>>>(ec, ec + NE, deg + 2 * NN, (const float4*)x, (float4*)aggc);

    // agg -> bf16 planes (applies dst norm)
    long aw = (long)MP * (KP1 / 4);
    int agrid = (int)((aw + 255) / 256);
    agg_convert_kernel<<<agrid, 256>>>((const float4*)aggr, deg + 1 * NN, aggr_h, aggr_l);
    agg_convert_kernel<<<agrid, 256>>>((const float4*)aggc, deg + 3 * NN, aggc_h, aggc_l);

    dim3 ggrid(NP / GBN, MP / GBM);   // (5, 782)

    // GraphConv GEMMs -> relu -> bf16 planes
    gemm_tc2_kernel<<<ggrid, 256, SMEM_TOTAL>>>(aggr_h, aggr_l, KP1, Wr_h, Wr_l, br,
        NN, DD, KP1 / GBK, 1, 1, nullptr, 0, rowg_h, rowg_l, KP1);
    gemm_tc2_kernel<<<ggrid, 256, SMEM_TOTAL>>>(aggc_h, aggc_l, KP1, Wc_h, Wc_l, bc,
        NN, DD, KP1 / GBK, 1, 1, nullptr, 0, colg_h, colg_l, KP1);

    // support GEMMs -> fp32 merged halves
    gemm_tc2_kernel<<<ggrid, 256, SMEM_TOTAL>>>(rowg_h, rowg_l, KP1, Wrs_h, Wrs_l, brs,
        NN, DD, KP1 / GBK, 0, 0, merged, 2 * DD, nullptr, nullptr, 0);
    gemm_tc2_kernel<<<ggrid, 256, SMEM_TOTAL>>>(colg_h, colg_l, KP1, Wcs_h, Wcs_l, bcs,
        NN, DD, KP1 / GBK, 0, 0, merged + DD, 2 * DD, nullptr, nullptr, 0);

    // LN both halves -> merged bf16 planes (+ pad cols); zero pad rows
    int lngrid = (NN + 7) / 8;
    ln_merged_kernel<<<lngrid, 256>>>(merged, g_rs, b_rs, g_cs, b_cs);
    zero_mrg_tail_kernel<<<128, 256>>>();

    // merge GEMM (K=600) -> fp32 out, then final LN
    gemm_tc2_kernel<<<ggrid, 256, SMEM_TOTAL>>>(mrg_h, mrg_l, KP2, Wm_h, Wm_l, bm,
        NN, DD, KP2 / GBK, 0, 0, out, DD, nullptr, nullptr, 0);
    ln_kernel<<<lngrid, 256>>>(out, DD, g_m, b_m, NN);
}